// round 8
// baseline (speedup 1.0000x reference)
#include <cuda_runtime.h>
#include <float.h>

// Problem shape (fixed by the dataset)
#define BSZ    2
#define SEQ    2048
#define DMODEL 1024
#define NH     16
#define DH     64
#define HIDN   1024
#define MROWS  (BSZ * SEQ)              // 4096

static const long long OUT_ELEMS  = (long long)BSZ * SEQ * DMODEL;   // 4,194,304
static const long long ATTN_ELEMS = (long long)BSZ * NH * SEQ * SEQ; // 134,217,728

// Scratch (allocation-free rule: __device__ globals)
__device__ float g_Q[BSZ * NH * SEQ * DH];
__device__ float g_K[BSZ * NH * SEQ * DH];
__device__ float g_V[BSZ * NH * SEQ * DH];
__device__ float g_mid[BSZ * SEQ * HIDN];
__device__ float g_attn_fb[BSZ * NH * SEQ * SEQ];

// ============================================================================
// gemm128: C = A @ W^T with A[M,K], W[N,K], both K-major.
// 128x128 tile, BK=8, 256 threads, 8x8 microtile (split 4+4 for LDS.128),
// double-buffered smem, register-staged global loads.
// MODE 0: C row-major [M,N]
// MODE 1: head-format write C[((b*NH+h)*SEQ+s)*DH + d], m=(b,s), n=(h,d)
// MODE 2: batched per-head scores: blockIdx.z = bh, A/W offset bh*SEQ*DH,
//         C offset bh*SEQ*SEQ (row-major SEQ x SEQ)
// ============================================================================
#define BM 128
#define BN 128
#define BK 8

template <int MODE>
__global__ void __launch_bounds__(256) gemm128_kernel(
    const float* __restrict__ A, const float* __restrict__ W,
    float* __restrict__ C, int M, int N, int K)
{
    if (MODE == 2) {
        const int bh = blockIdx.z;
        A += (size_t)bh * SEQ * DH;
        W += (size_t)bh * SEQ * DH;
        C += (size_t)bh * SEQ * SEQ;
    }

    __shared__ __align__(16) float As[2][BK][BM];
    __shared__ __align__(16) float Bs[2][BK][BN];

    const int tid   = threadIdx.x;
    const int tx    = tid & 15;          // 0..15 -> cols
    const int ty    = tid >> 4;          // 0..15 -> rows
    const int mBase = blockIdx.y * BM;
    const int nBase = blockIdx.x * BN;

    const int lrow = tid >> 1;           // 0..127
    const int lk   = (tid & 1) << 2;     // 0 or 4

    const float* Ap = A + (size_t)(mBase + lrow) * K + lk;
    const float* Wp = W + (size_t)(nBase + lrow) * K + lk;

    float acc[2][2][4][4] = {};

    // Prologue: tile 0 -> buffer 0
    {
        float4 a0 = *(const float4*)Ap;
        float4 w0 = *(const float4*)Wp;
        As[0][lk + 0][lrow] = a0.x; As[0][lk + 1][lrow] = a0.y;
        As[0][lk + 2][lrow] = a0.z; As[0][lk + 3][lrow] = a0.w;
        Bs[0][lk + 0][lrow] = w0.x; Bs[0][lk + 1][lrow] = w0.y;
        Bs[0][lk + 2][lrow] = w0.z; Bs[0][lk + 3][lrow] = w0.w;
    }
    __syncthreads();

    int buf = 0;
    for (int k0 = 0; k0 < K; k0 += BK) {
        float4 na, nw;
        const bool more = (k0 + BK) < K;
        if (more) {
            na = *(const float4*)(Ap + k0 + BK);
            nw = *(const float4*)(Wp + k0 + BK);
        }
#pragma unroll
        for (int kk = 0; kk < BK; kk++) {
            float4 a0 = *(const float4*)&As[buf][kk][ty * 4];
            float4 a1 = *(const float4*)&As[buf][kk][ty * 4 + 64];
            float4 b0 = *(const float4*)&Bs[buf][kk][tx * 4];
            float4 b1 = *(const float4*)&Bs[buf][kk][tx * 4 + 64];
            float ar[8] = {a0.x, a0.y, a0.z, a0.w, a1.x, a1.y, a1.z, a1.w};
            float br[8] = {b0.x, b0.y, b0.z, b0.w, b1.x, b1.y, b1.z, b1.w};
#pragma unroll
            for (int ii = 0; ii < 2; ii++)
#pragma unroll
            for (int i = 0; i < 4; i++)
#pragma unroll
            for (int jj = 0; jj < 2; jj++)
#pragma unroll
            for (int j = 0; j < 4; j++)
                acc[ii][jj][i][j] += ar[ii * 4 + i] * br[jj * 4 + j];
        }
        if (more) {
            const int nb = buf ^ 1;
            As[nb][lk + 0][lrow] = na.x; As[nb][lk + 1][lrow] = na.y;
            As[nb][lk + 2][lrow] = na.z; As[nb][lk + 3][lrow] = na.w;
            Bs[nb][lk + 0][lrow] = nw.x; Bs[nb][lk + 1][lrow] = nw.y;
            Bs[nb][lk + 2][lrow] = nw.z; Bs[nb][lk + 3][lrow] = nw.w;
        }
        __syncthreads();
        buf ^= 1;
    }

#pragma unroll
    for (int ii = 0; ii < 2; ii++)
#pragma unroll
    for (int i = 0; i < 4; i++) {
        const int m = mBase + ii * 64 + ty * 4 + i;
#pragma unroll
        for (int jj = 0; jj < 2; jj++) {
            const int n = nBase + jj * 64 + tx * 4;
            float4 v = make_float4(acc[ii][jj][i][0], acc[ii][jj][i][1],
                                   acc[ii][jj][i][2], acc[ii][jj][i][3]);
            if (MODE == 1) {
                const int b_ = m >> 11;          // m / SEQ
                const int s_ = m & (SEQ - 1);
                const int h_ = n >> 6;           // n / DH (d spans tx*4..+3, same head)
                const int d_ = n & (DH - 1);
                *(float4*)&C[((size_t)(b_ * NH + h_) * SEQ + s_) * DH + d_] = v;
            } else {
                *(float4*)&C[(size_t)m * N + n] = v;
            }
        }
    }
}

// ============================================================================
// Softmax, in-place over last dim (SEQ), one block per row.
// Mask loaded ONCE into smem as additive bias (0 / -FLT_MAX); float4 I/O;
// __expf. Mask dtype defense (byte vs int32) as before.
// ============================================================================
__global__ void __launch_bounds__(256) softmax_kernel(
    float* __restrict__ attn, const unsigned char* __restrict__ mask)
{
    const int row = blockIdx.x;              // 0 .. BSZ*NH*SEQ-1
    const int b   = row >> 15;               // row / (NH*SEQ)
    float* rp = attn + (size_t)row * SEQ;

    __shared__ __align__(16) float bias[SEQ];
    __shared__ float red[8];

    const int stride =
        (mask[0] == 1 && mask[1] == 0 && mask[2] == 0 && mask[3] == 0) ? 4 : 1;
    const unsigned char* mb = mask + (size_t)b * SEQ * stride;

    const int tid = threadIdx.x;
    for (int j = tid; j < SEQ; j += 256)
        bias[j] = mb[(size_t)j * stride] ? 0.f : -FLT_MAX;
    __syncthreads();

    const int j0 = tid << 3;
    float4 u0 = *(const float4*)&rp[j0];
    float4 u1 = *(const float4*)&rp[j0 + 4];
    float4 c0 = *(const float4*)&bias[j0];
    float4 c1 = *(const float4*)&bias[j0 + 4];
    float v[8] = {u0.x + c0.x, u0.y + c0.y, u0.z + c0.z, u0.w + c0.w,
                  u1.x + c1.x, u1.y + c1.y, u1.z + c1.z, u1.w + c1.w};

    float mx = v[0];
#pragma unroll
    for (int i = 1; i < 8; i++) mx = fmaxf(mx, v[i]);
#pragma unroll
    for (int o = 16; o > 0; o >>= 1) mx = fmaxf(mx, __shfl_xor_sync(0xffffffffu, mx, o));
    if ((tid & 31) == 0) red[tid >> 5] = mx;
    __syncthreads();
    float fmx = red[0];
#pragma unroll
    for (int i = 1; i < 8; i++) fmx = fmaxf(fmx, red[i]);

    float sum = 0.f;
#pragma unroll
    for (int i = 0; i < 8; i++) { v[i] = __expf(v[i] - fmx); sum += v[i]; }
#pragma unroll
    for (int o = 16; o > 0; o >>= 1) sum += __shfl_xor_sync(0xffffffffu, sum, o);
    __syncthreads();
    if ((tid & 31) == 0) red[tid >> 5] = sum;
    __syncthreads();
    float tot = 0.f;
#pragma unroll
    for (int i = 0; i < 8; i++) tot += red[i];
    const float inv = 1.f / tot;

    float4 w0 = make_float4(v[0] * inv, v[1] * inv, v[2] * inv, v[3] * inv);
    float4 w1 = make_float4(v[4] * inv, v[5] * inv, v[6] * inv, v[7] * inv);
    *(float4*)&rp[j0]     = w0;
    *(float4*)&rp[j0 + 4] = w1;
}

// ============================================================================
// AV: mid[b][i][h*DH+n] = scale * sum_j attn[bh][i][j] * V[bh][j][n]
// 128x64 tile, BK=16, 256 threads, 8x4 microtile, double-buffered smem.
// ============================================================================
#define AM 128
#define AN 64
#define AK 16

__global__ void __launch_bounds__(256) av_kernel(
    const float* __restrict__ attn, const float* __restrict__ V,
    float* __restrict__ mid)
{
    const int bh = blockIdx.z;
    const int b  = bh >> 4;
    const int h  = bh & 15;
    const float* A  = attn + (size_t)bh * SEQ * SEQ;
    const float* Vb = V    + (size_t)bh * SEQ * DH;

    __shared__ __align__(16) float As[2][AK][AM];
    __shared__ __align__(16) float Bs[2][AK][AN];

    const int tid   = threadIdx.x;
    const int tx    = tid & 15;          // cols: tx*4 (0..60)
    const int ty    = tid >> 4;          // rows: ty*4 and +64
    const int mBase = blockIdx.y * AM;

    const int arow = tid >> 2;           // 0..63 (and +64)
    const int akc  = (tid & 3) << 2;     // 0,4,8,12
    const int vrow = tid >> 4;           // 0..15
    const int vcol = (tid & 15) << 2;    // 0..60

    const float* Ap0 = A + (size_t)(mBase + arow) * SEQ + akc;
    const float* Ap1 = Ap0 + (size_t)64 * SEQ;
    const float* Vp  = Vb + (size_t)vrow * DH + vcol;

    float acc[2][4][4] = {};

    {
        float4 a0 = *(const float4*)Ap0;
        float4 a1 = *(const float4*)Ap1;
        float4 vv = *(const float4*)Vp;
        As[0][akc + 0][arow] = a0.x; As[0][akc + 1][arow] = a0.y;
        As[0][akc + 2][arow] = a0.z; As[0][akc + 3][arow] = a0.w;
        As[0][akc + 0][arow + 64] = a1.x; As[0][akc + 1][arow + 64] = a1.y;
        As[0][akc + 2][arow + 64] = a1.z; As[0][akc + 3][arow + 64] = a1.w;
        *(float4*)&Bs[0][vrow][vcol] = vv;
    }
    __syncthreads();

    int buf = 0;
    for (int k0 = 0; k0 < SEQ; k0 += AK) {
        float4 na0, na1, nv;
        const bool more = (k0 + AK) < SEQ;
        if (more) {
            na0 = *(const float4*)(Ap0 + k0 + AK);
            na1 = *(const float4*)(Ap1 + k0 + AK);
            nv  = *(const float4*)(Vp + (size_t)(k0 + AK) * DH);
        }
#pragma unroll
        for (int kk = 0; kk < AK; kk++) {
            float4 a0 = *(const float4*)&As[buf][kk][ty * 4];
            float4 a1 = *(const float4*)&As[buf][kk][ty * 4 + 64];
            float4 bv = *(const float4*)&Bs[buf][kk][tx * 4];
            float ar[8] = {a0.x, a0.y, a0.z, a0.w, a1.x, a1.y, a1.z, a1.w};
            float br[4] = {bv.x, bv.y, bv.z, bv.w};
#pragma unroll
            for (int ii = 0; ii < 2; ii++)
#pragma unroll
            for (int i = 0; i < 4; i++)
#pragma unroll
            for (int j = 0; j < 4; j++)
                acc[ii][i][j] += ar[ii * 4 + i] * br[j];
        }
        if (more) {
            const int nb = buf ^ 1;
            As[nb][akc + 0][arow] = na0.x; As[nb][akc + 1][arow] = na0.y;
            As[nb][akc + 2][arow] = na0.z; As[nb][akc + 3][arow] = na0.w;
            As[nb][akc + 0][arow + 64] = na1.x; As[nb][akc + 1][arow + 64] = na1.y;
            As[nb][akc + 2][arow + 64] = na1.z; As[nb][akc + 3][arow + 64] = na1.w;
            *(float4*)&Bs[nb][vrow][vcol] = nv;
        }
        __syncthreads();
        buf ^= 1;
    }

    const float scale = 0.03125f;  // HID^(-0.5) = 1/32
#pragma unroll
    for (int ii = 0; ii < 2; ii++)
#pragma unroll
    for (int i = 0; i < 4; i++) {
        const int m = mBase + ii * 64 + ty * 4 + i;
        float4 v = make_float4(acc[ii][i][0] * scale, acc[ii][i][1] * scale,
                               acc[ii][i][2] * scale, acc[ii][i][3] * scale);
        *(float4*)&mid[((size_t)b * SEQ + m) * HIDN + h * DH + tx * 4] = v;
    }
}

extern "C" void kernel_launch(void* const* d_in, const int* in_sizes, int n_in,
                              void* d_out, int out_size)
{
    const float*         x    = (const float*)d_in[0];
    const unsigned char* mask = (const unsigned char*)d_in[1];
    const float*         Wq   = (const float*)d_in[2];
    const float*         Wk   = (const float*)d_in[3];
    const float*         Wv   = (const float*)d_in[4];
    const float*         Wo   = (const float*)d_in[5];
    float* out = (float*)d_out;

    void *pq, *pk, *pv, *pm;
    cudaGetSymbolAddress(&pq, g_Q);
    cudaGetSymbolAddress(&pk, g_K);
    cudaGetSymbolAddress(&pv, g_V);
    cudaGetSymbolAddress(&pm, g_mid);
    float* q   = (float*)pq;
    float* k   = (float*)pk;
    float* v   = (float*)pv;
    float* mid = (float*)pm;

    // attn goes straight into the output buffer (outputs concatenated in
    // reference-return order: out, then attn). Fallback to scratch otherwise.
    float* attn;
    if ((long long)out_size >= OUT_ELEMS + ATTN_ELEMS) {
        attn = out + OUT_ELEMS;
    } else {
        void* pa;
        cudaGetSymbolAddress(&pa, g_attn_fb);
        attn = (float*)pa;
    }

    dim3 projGrid(HIDN / BN, MROWS / BM);   // (8, 32)
    gemm128_kernel<1><<<projGrid, 256>>>(x, Wq, q, MROWS, HIDN, DMODEL);
    gemm128_kernel<1><<<projGrid, 256>>>(x, Wk, k, MROWS, HIDN, DMODEL);
    gemm128_kernel<1><<<projGrid, 256>>>(x, Wv, v, MROWS, HIDN, DMODEL);

    gemm128_kernel<2><<<dim3(SEQ / BN, SEQ / BM, BSZ * NH), 256>>>(
        q, k, attn, SEQ, SEQ, DH);

    softmax_kernel<<<BSZ * NH * SEQ, 256>>>(attn, mask);

    av_kernel<<<dim3(1, SEQ / AM, BSZ * NH), 256>>>(attn, v, mid);

    gemm128_kernel<0><<<dim3(DMODEL / BN, MROWS / BM), 256>>>(
        mid, Wo, out, MROWS, DMODEL, HIDN);
}

// round 10
// speedup vs baseline: 1.0042x; 1.0042x over previous
#include <cuda_runtime.h>
#include <float.h>

// Problem shape (fixed by the dataset)
#define BSZ    2
#define SEQ    2048
#define DMODEL 1024
#define NH     16
#define DH     64
#define HIDN   1024
#define MROWS  (BSZ * SEQ)              // 4096

static const long long OUT_ELEMS  = (long long)BSZ * SEQ * DMODEL;   // 4,194,304
static const long long ATTN_ELEMS = (long long)BSZ * NH * SEQ * SEQ; // 134,217,728

// Scratch (allocation-free rule: __device__ globals)
__device__ float g_Q[BSZ * NH * SEQ * DH];
__device__ float g_K[BSZ * NH * SEQ * DH];
__device__ float g_V[BSZ * NH * SEQ * DH];
__device__ float g_mid[BSZ * SEQ * HIDN];
__device__ float g_attn_fb[BSZ * NH * SEQ * SEQ];

// ============================================================================
// gemm128: C = A @ W^T with A[M,K], W[N,K], both K-major.
// 128x128 tile, BK=8, 256 threads, 8x8 microtile (split 4+4 for LDS.128),
// double-buffered smem, register-staged global loads.
// MODE 0: C row-major [M,N]
// MODE 1: head-format write C[((b*NH+h)*SEQ+s)*DH + d], m=(b,s), n=(h,d)
// MODE 2: batched per-head scores: blockIdx.z = bh, A/W offset bh*SEQ*DH,
//         C offset bh*SEQ*SEQ (row-major SEQ x SEQ)
// ============================================================================
#define BM 128
#define BN 128
#define BK 8

template <int MODE>
__global__ void __launch_bounds__(256) gemm128_kernel(
    const float* __restrict__ A, const float* __restrict__ W,
    float* __restrict__ C, int M, int N, int K)
{
    if (MODE == 2) {
        const int bh = blockIdx.z;
        A += (size_t)bh * SEQ * DH;
        W += (size_t)bh * SEQ * DH;
        C += (size_t)bh * SEQ * SEQ;
    }

    __shared__ __align__(16) float As[2][BK][BM];
    __shared__ __align__(16) float Bs[2][BK][BN];

    const int tid   = threadIdx.x;
    const int tx    = tid & 15;          // 0..15 -> cols
    const int ty    = tid >> 4;          // 0..15 -> rows
    const int mBase = blockIdx.y * BM;
    const int nBase = blockIdx.x * BN;

    const int lrow = tid >> 1;           // 0..127
    const int lk   = (tid & 1) << 2;     // 0 or 4

    const float* Ap = A + (size_t)(mBase + lrow) * K + lk;
    const float* Wp = W + (size_t)(nBase + lrow) * K + lk;

    float acc[2][2][4][4] = {};

    // Prologue: tile 0 -> buffer 0
    {
        float4 a0 = *(const float4*)Ap;
        float4 w0 = *(const float4*)Wp;
        As[0][lk + 0][lrow] = a0.x; As[0][lk + 1][lrow] = a0.y;
        As[0][lk + 2][lrow] = a0.z; As[0][lk + 3][lrow] = a0.w;
        Bs[0][lk + 0][lrow] = w0.x; Bs[0][lk + 1][lrow] = w0.y;
        Bs[0][lk + 2][lrow] = w0.z; Bs[0][lk + 3][lrow] = w0.w;
    }
    __syncthreads();

    int buf = 0;
    for (int k0 = 0; k0 < K; k0 += BK) {
        float4 na, nw;
        const bool more = (k0 + BK) < K;
        if (more) {
            na = *(const float4*)(Ap + k0 + BK);
            nw = *(const float4*)(Wp + k0 + BK);
        }
#pragma unroll
        for (int kk = 0; kk < BK; kk++) {
            float4 a0 = *(const float4*)&As[buf][kk][ty * 4];
            float4 a1 = *(const float4*)&As[buf][kk][ty * 4 + 64];
            float4 b0 = *(const float4*)&Bs[buf][kk][tx * 4];
            float4 b1 = *(const float4*)&Bs[buf][kk][tx * 4 + 64];
            float ar[8] = {a0.x, a0.y, a0.z, a0.w, a1.x, a1.y, a1.z, a1.w};
            float br[8] = {b0.x, b0.y, b0.z, b0.w, b1.x, b1.y, b1.z, b1.w};
#pragma unroll
            for (int ii = 0; ii < 2; ii++)
#pragma unroll
            for (int i = 0; i < 4; i++)
#pragma unroll
            for (int jj = 0; jj < 2; jj++)
#pragma unroll
            for (int j = 0; j < 4; j++)
                acc[ii][jj][i][j] += ar[ii * 4 + i] * br[jj * 4 + j];
        }
        if (more) {
            const int nb = buf ^ 1;
            As[nb][lk + 0][lrow] = na.x; As[nb][lk + 1][lrow] = na.y;
            As[nb][lk + 2][lrow] = na.z; As[nb][lk + 3][lrow] = na.w;
            Bs[nb][lk + 0][lrow] = nw.x; Bs[nb][lk + 1][lrow] = nw.y;
            Bs[nb][lk + 2][lrow] = nw.z; Bs[nb][lk + 3][lrow] = nw.w;
        }
        __syncthreads();
        buf ^= 1;
    }

#pragma unroll
    for (int ii = 0; ii < 2; ii++)
#pragma unroll
    for (int i = 0; i < 4; i++) {
        const int m = mBase + ii * 64 + ty * 4 + i;
#pragma unroll
        for (int jj = 0; jj < 2; jj++) {
            const int n = nBase + jj * 64 + tx * 4;
            float4 v = make_float4(acc[ii][jj][i][0], acc[ii][jj][i][1],
                                   acc[ii][jj][i][2], acc[ii][jj][i][3]);
            if (MODE == 1) {
                const int b_ = m >> 11;          // m / SEQ
                const int s_ = m & (SEQ - 1);
                const int h_ = n >> 6;           // n / DH (d spans tx*4..+3, same head)
                const int d_ = n & (DH - 1);
                *(float4*)&C[((size_t)(b_ * NH + h_) * SEQ + s_) * DH + d_] = v;
            } else {
                *(float4*)&C[(size_t)m * N + n] = v;
            }
        }
    }
}

// ============================================================================
// Softmax, in-place over last dim (SEQ), one block per row.
// Mask loaded ONCE into smem as additive bias (0 / -FLT_MAX); float4 I/O;
// __expf. Mask dtype defense (byte vs int32) as before.
// ============================================================================
__global__ void __launch_bounds__(256) softmax_kernel(
    float* __restrict__ attn, const unsigned char* __restrict__ mask)
{
    const int row = blockIdx.x;              // 0 .. BSZ*NH*SEQ-1
    const int b   = row >> 15;               // row / (NH*SEQ)
    float* rp = attn + (size_t)row * SEQ;

    __shared__ __align__(16) float bias[SEQ];
    __shared__ float red[8];

    const int stride =
        (mask[0] == 1 && mask[1] == 0 && mask[2] == 0 && mask[3] == 0) ? 4 : 1;
    const unsigned char* mb = mask + (size_t)b * SEQ * stride;

    const int tid = threadIdx.x;
    for (int j = tid; j < SEQ; j += 256)
        bias[j] = mb[(size_t)j * stride] ? 0.f : -FLT_MAX;
    __syncthreads();

    const int j0 = tid << 3;
    float4 u0 = *(const float4*)&rp[j0];
    float4 u1 = *(const float4*)&rp[j0 + 4];
    float4 c0 = *(const float4*)&bias[j0];
    float4 c1 = *(const float4*)&bias[j0 + 4];
    float v[8] = {u0.x + c0.x, u0.y + c0.y, u0.z + c0.z, u0.w + c0.w,
                  u1.x + c1.x, u1.y + c1.y, u1.z + c1.z, u1.w + c1.w};

    float mx = v[0];
#pragma unroll
    for (int i = 1; i < 8; i++) mx = fmaxf(mx, v[i]);
#pragma unroll
    for (int o = 16; o > 0; o >>= 1) mx = fmaxf(mx, __shfl_xor_sync(0xffffffffu, mx, o));
    if ((tid & 31) == 0) red[tid >> 5] = mx;
    __syncthreads();
    float fmx = red[0];
#pragma unroll
    for (int i = 1; i < 8; i++) fmx = fmaxf(fmx, red[i]);

    float sum = 0.f;
#pragma unroll
    for (int i = 0; i < 8; i++) { v[i] = __expf(v[i] - fmx); sum += v[i]; }
#pragma unroll
    for (int o = 16; o > 0; o >>= 1) sum += __shfl_xor_sync(0xffffffffu, sum, o);
    __syncthreads();
    if ((tid & 31) == 0) red[tid >> 5] = sum;
    __syncthreads();
    float tot = 0.f;
#pragma unroll
    for (int i = 0; i < 8; i++) tot += red[i];
    const float inv = 1.f / tot;

    float4 w0 = make_float4(v[0] * inv, v[1] * inv, v[2] * inv, v[3] * inv);
    float4 w1 = make_float4(v[4] * inv, v[5] * inv, v[6] * inv, v[7] * inv);
    *(float4*)&rp[j0]     = w0;
    *(float4*)&rp[j0 + 4] = w1;
}

// ============================================================================
// AV: mid[b][i][h*DH+n] = scale * sum_j attn[bh][i][j] * V[bh][j][n]
// 128x64 tile, BK=16, 256 threads, 8x4 microtile, double-buffered smem.
// ============================================================================
#define AM 128
#define AN 64
#define AK 16

__global__ void __launch_bounds__(256) av_kernel(
    const float* __restrict__ attn, const float* __restrict__ V,
    float* __restrict__ mid)
{
    const int bh = blockIdx.z;
    const int b  = bh >> 4;
    const int h  = bh & 15;
    const float* A  = attn + (size_t)bh * SEQ * SEQ;
    const float* Vb = V    + (size_t)bh * SEQ * DH;

    __shared__ __align__(16) float As[2][AK][AM];
    __shared__ __align__(16) float Bs[2][AK][AN];

    const int tid   = threadIdx.x;
    const int tx    = tid & 15;          // cols: tx*4 (0..60)
    const int ty    = tid >> 4;          // rows: ty*4 and +64
    const int mBase = blockIdx.y * AM;

    const int arow = tid >> 2;           // 0..63 (and +64)
    const int akc  = (tid & 3) << 2;     // 0,4,8,12
    const int vrow = tid >> 4;           // 0..15
    const int vcol = (tid & 15) << 2;    // 0..60

    const float* Ap0 = A + (size_t)(mBase + arow) * SEQ + akc;
    const float* Ap1 = Ap0 + (size_t)64 * SEQ;
    const float* Vp  = Vb + (size_t)vrow * DH + vcol;

    float acc[2][4][4] = {};

    {
        float4 a0 = *(const float4*)Ap0;
        float4 a1 = *(const float4*)Ap1;
        float4 vv = *(const float4*)Vp;
        As[0][akc + 0][arow] = a0.x; As[0][akc + 1][arow] = a0.y;
        As[0][akc + 2][arow] = a0.z; As[0][akc + 3][arow] = a0.w;
        As[0][akc + 0][arow + 64] = a1.x; As[0][akc + 1][arow + 64] = a1.y;
        As[0][akc + 2][arow + 64] = a1.z; As[0][akc + 3][arow + 64] = a1.w;
        *(float4*)&Bs[0][vrow][vcol] = vv;
    }
    __syncthreads();

    int buf = 0;
    for (int k0 = 0; k0 < SEQ; k0 += AK) {
        float4 na0, na1, nv;
        const bool more = (k0 + AK) < SEQ;
        if (more) {
            na0 = *(const float4*)(Ap0 + k0 + AK);
            na1 = *(const float4*)(Ap1 + k0 + AK);
            nv  = *(const float4*)(Vp + (size_t)(k0 + AK) * DH);
        }
#pragma unroll
        for (int kk = 0; kk < AK; kk++) {
            float4 a0 = *(const float4*)&As[buf][kk][ty * 4];
            float4 a1 = *(const float4*)&As[buf][kk][ty * 4 + 64];
            float4 bv = *(const float4*)&Bs[buf][kk][tx * 4];
            float ar[8] = {a0.x, a0.y, a0.z, a0.w, a1.x, a1.y, a1.z, a1.w};
            float br[4] = {bv.x, bv.y, bv.z, bv.w};
#pragma unroll
            for (int ii = 0; ii < 2; ii++)
#pragma unroll
            for (int i = 0; i < 4; i++)
#pragma unroll
            for (int j = 0; j < 4; j++)
                acc[ii][i][j] += ar[ii * 4 + i] * br[j];
        }
        if (more) {
            const int nb = buf ^ 1;
            As[nb][akc + 0][arow] = na0.x; As[nb][akc + 1][arow] = na0.y;
            As[nb][akc + 2][arow] = na0.z; As[nb][akc + 3][arow] = na0.w;
            As[nb][akc + 0][arow + 64] = na1.x; As[nb][akc + 1][arow + 64] = na1.y;
            As[nb][akc + 2][arow + 64] = na1.z; As[nb][akc + 3][arow + 64] = na1.w;
            *(float4*)&Bs[nb][vrow][vcol] = nv;
        }
        __syncthreads();
        buf ^= 1;
    }

    const float scale = 0.03125f;  // HID^(-0.5) = 1/32
#pragma unroll
    for (int ii = 0; ii < 2; ii++)
#pragma unroll
    for (int i = 0; i < 4; i++) {
        const int m = mBase + ii * 64 + ty * 4 + i;
        float4 v = make_float4(acc[ii][i][0] * scale, acc[ii][i][1] * scale,
                               acc[ii][i][2] * scale, acc[ii][i][3] * scale);
        *(float4*)&mid[((size_t)b * SEQ + m) * HIDN + h * DH + tx * 4] = v;
    }
}

extern "C" void kernel_launch(void* const* d_in, const int* in_sizes, int n_in,
                              void* d_out, int out_size)
{
    const float*         x    = (const float*)d_in[0];
    const unsigned char* mask = (const unsigned char*)d_in[1];
    const float*         Wq   = (const float*)d_in[2];
    const float*         Wk   = (const float*)d_in[3];
    const float*         Wv   = (const float*)d_in[4];
    const float*         Wo   = (const float*)d_in[5];
    float* out = (float*)d_out;

    void *pq, *pk, *pv, *pm;
    cudaGetSymbolAddress(&pq, g_Q);
    cudaGetSymbolAddress(&pk, g_K);
    cudaGetSymbolAddress(&pv, g_V);
    cudaGetSymbolAddress(&pm, g_mid);
    float* q   = (float*)pq;
    float* k   = (float*)pk;
    float* v   = (float*)pv;
    float* mid = (float*)pm;

    // attn goes straight into the output buffer (outputs concatenated in
    // reference-return order: out, then attn). Fallback to scratch otherwise.
    float* attn;
    if ((long long)out_size >= OUT_ELEMS + ATTN_ELEMS) {
        attn = out + OUT_ELEMS;
    } else {
        void* pa;
        cudaGetSymbolAddress(&pa, g_attn_fb);
        attn = (float*)pa;
    }

    dim3 projGrid(HIDN / BN, MROWS / BM);   // (8, 32)
    gemm128_kernel<1><<<projGrid, 256>>>(x, Wq, q, MROWS, HIDN, DMODEL);
    gemm128_kernel<1><<<projGrid, 256>>>(x, Wk, k, MROWS, HIDN, DMODEL);
    gemm128_kernel<1><<<projGrid, 256>>>(x, Wv, v, MROWS, HIDN, DMODEL);

    gemm128_kernel<2><<<dim3(SEQ / BN, SEQ / BM, BSZ * NH), 256>>>(
        q, k, attn, SEQ, SEQ, DH);

    softmax_kernel<<<BSZ * NH * SEQ, 256>>>(attn, mask);

    av_kernel<<<dim3(1, SEQ / AM, BSZ * NH), 256>>>(attn, v, mid);

    gemm128_kernel<0><<<dim3(DMODEL / BN, MROWS / BM), 256>>>(
        mid, Wo, out, MROWS, DMODEL, HIDN);
}